// round 16
// baseline (speedup 1.0000x reference)
#include <cuda_runtime.h>
#include <math.h>

#define B1n 4
#define B2n 1024
#define Rn  64
#define Tn  8192
#define Ln  256

// 256 threads = 64 l-threads x 4 r-groups (16 receivers each).
// Receivers counting-sorted by d = i0 & 3. Four d-specialized sub-loops;
// every receiver costs ONE LDG.128 + <=2 SHFL; warp-edge lanes patched by
// predicated scalar loads (issued before the shuffles).

template<int D>
__device__ __forceinline__ void body_d(float2 pr, const float* recb,
                                       bool lo_edge, bool hi_edge,
                                       float& a0, float& a1, float& a2, float& a3,
                                       float& q0, float& q1, float& q2, float& q3)
{
    const unsigned FULL = 0xFFFFFFFFu;
    float f = pr.x;
    int   o = __float_as_int(pr.y);
    const float*  fp = recb + (o >> 2);
    const float4* p4 = (const float4*)fp;

    float w0, w1, w2, w3, w4;
    if (D == 0) {
        float4 A = __ldg(p4);                        // elements 4t..4t+3
        float p0 = 0.0f;
        if (hi_edge) p0 = __ldg(fp + 4);
        float n0 = __shfl_down_sync(FULL, A.x, 1);   // element 4t+4
        if (hi_edge) n0 = p0;
        w0 = A.x; w1 = A.y; w2 = A.z; w3 = A.w; w4 = n0;
    } else if (D == 1) {
        float4 A = __ldg(p4);
        float p0 = 0.0f, p1 = 0.0f;
        if (hi_edge) { p0 = __ldg(fp + 4); p1 = __ldg(fp + 5); }
        float n0 = __shfl_down_sync(FULL, A.x, 1);   // 4t+4
        float n1 = __shfl_down_sync(FULL, A.y, 1);   // 4t+5
        if (hi_edge) { n0 = p0; n1 = p1; }
        w0 = A.y; w1 = A.z; w2 = A.w; w3 = n0; w4 = n1;
    } else if (D == 2) {
        float4 B = __ldg(p4 + 1);                    // elements 4t+4..4t+7
        float p0 = 0.0f, p1 = 0.0f;
        if (lo_edge) { p0 = __ldg(fp + 2); p1 = __ldg(fp + 3); }
        float pz = __shfl_up_sync(FULL, B.z, 1);     // 4t+2
        float pw = __shfl_up_sync(FULL, B.w, 1);     // 4t+3
        if (lo_edge) { pz = p0; pw = p1; }
        w0 = pz; w1 = pw; w2 = B.x; w3 = B.y; w4 = B.z;
    } else {
        float4 B = __ldg(p4 + 1);
        float p0 = 0.0f;
        if (lo_edge) p0 = __ldg(fp + 3);
        float pw = __shfl_up_sync(FULL, B.w, 1);     // 4t+3
        if (lo_edge) pw = p0;
        w0 = pw; w1 = B.x; w2 = B.y; w3 = B.z; w4 = B.w;
    }

    float e0 = fmaf(f, w1 - w0, w0);
    float e1 = fmaf(f, w2 - w1, w1);
    float e2 = fmaf(f, w3 - w2, w2);
    float e3 = fmaf(f, w4 - w3, w3);
    a0 += e0; q0 = fmaf(e0, e0, q0);
    a1 += e1; q1 = fmaf(e1, e1, q1);
    a2 += e2; q2 = fmaf(e2, e2, q2);
    a3 += e3; q3 = fmaf(e3, e3, q3);
}

__global__ void __launch_bounds__(Ln)
tof_predictor_kernel(const float* __restrict__ rec,        // (B1,R,T)
                     const float* __restrict__ samp,       // (B1,B2,3)
                     const float* __restrict__ emit,       // (3,)
                     const float* __restrict__ recv,       // (R,3)
                     float* __restrict__ out)              // (B1,B2)
{
    const int b2  = blockIdx.x;
    const int b1  = blockIdx.y;
    const int tid = threadIdx.x;

    __shared__ float2 s_sorted[Rn];
    __shared__ int    s_cnt[4][4];
    __shared__ int    s_start[4][4];
    __shared__ int    s_bnd[4][4];
    __shared__ float  s_s1[4 * Ln];
    __shared__ float  s_s2[4 * Ln];
    __shared__ float  s_red[16];

    // ---- precompute + deterministic counting sort by d (threads 0..63) ----
    const float fs_c = 96000.0f / 343.0f;
    if (tid < 16) s_cnt[tid >> 2][tid & 3] = 0;
    __syncthreads();

    float2 packed;
    int my_d = 0, my_rank = 0, my_g = 0;
    if (tid < Rn) {
        const float* sp = samp + ((size_t)b1 * B2n + b2) * 3;
        float sx = sp[0], sy = sp[1], sz = sp[2];
        float ex = sx - emit[0], ey = sy - emit[1], ez = sz - emit[2];
        float d_e = sqrtf(ex * ex + ey * ey + ez * ez);
        const float* rp = recv + tid * 3;
        float rx = sx - rp[0], ry = sy - rp[1], rz = sz - rp[2];
        float d_r = sqrtf(rx * rx + ry * ry + rz * rz);
        float start = (d_e + d_r) * fs_c;
        int i0 = (int)floorf(start);
        i0 = min(max(i0, 0), Tn - 2 - (Ln - 1) - 7);  // never fires in practice
        float frac = start - (float)i0;
        int i0a = i0 & ~3;
        my_d = i0 & 3;
        my_g = tid >> 4;
        packed = make_float2(frac, __int_as_float((tid * Tn + i0a) << 2));

        unsigned m = __match_any_sync(0xFFFFFFFFu, (my_g << 2) | my_d);
        unsigned lt = m & ((1u << (tid & 31)) - 1u);
        my_rank = __popc(lt);
        if (lt == 0u) s_cnt[my_g][my_d] = __popc(m);
    }
    __syncthreads();
    if (tid < 4) {
        int c0 = s_cnt[tid][0], c1 = s_cnt[tid][1], c2 = s_cnt[tid][2], c3 = s_cnt[tid][3];
        int o0 = 0, o1 = c0, o2 = c0 + c1, o3 = c0 + c1 + c2;
        s_start[tid][0] = o0; s_start[tid][1] = o1; s_start[tid][2] = o2; s_start[tid][3] = o3;
        s_bnd[tid][0] = o1; s_bnd[tid][1] = o2; s_bnd[tid][2] = o3; s_bnd[tid][3] = 16;
    }
    __syncthreads();
    if (tid < Rn) {
        s_sorted[my_g * 16 + s_start[my_g][my_d] + my_rank] = packed;
    }
    __syncthreads();

    const int g = tid >> 6;
    const int t = tid & 63;
    const int lane = tid & 31;
    const bool lo_edge = (lane == 0);
    const bool hi_edge = (lane == 31);

    const float* recb = rec + (size_t)b1 * Rn * Tn + 4 * t;

    float a0 = 0.f, a1 = 0.f, a2 = 0.f, a3 = 0.f;
    float q0 = 0.f, q1 = 0.f, q2 = 0.f, q3 = 0.f;

    const int base = g * 16;
    const int e0b = s_bnd[g][0];
    const int e1b = s_bnd[g][1];
    const int e2b = s_bnd[g][2];

    int k = 0;
    for (; k < e0b; ++k)
        body_d<0>(s_sorted[base + k], recb, lo_edge, hi_edge, a0, a1, a2, a3, q0, q1, q2, q3);
    for (; k < e1b; ++k)
        body_d<1>(s_sorted[base + k], recb, lo_edge, hi_edge, a0, a1, a2, a3, q0, q1, q2, q3);
    for (; k < e2b; ++k)
        body_d<2>(s_sorted[base + k], recb, lo_edge, hi_edge, a0, a1, a2, a3, q0, q1, q2, q3);
    for (; k < 16; ++k)
        body_d<3>(s_sorted[base + k], recb, lo_edge, hi_edge, a0, a1, a2, a3, q0, q1, q2, q3);

    // store per-group partials
    {
        float4* p1 = (float4*)&s_s1[g * Ln + 4 * t];
        float4* p2 = (float4*)&s_s2[g * Ln + 4 * t];
        *p1 = make_float4(a0, a1, a2, a3);
        *p2 = make_float4(q0, q1, q2, q3);
    }
    __syncthreads();

    // combine across the 4 r-groups: thread tid owns l = tid
    float S1 = s_s1[tid] + s_s1[Ln + tid] + s_s1[2 * Ln + tid] + s_s1[3 * Ln + tid];
    float S2 = s_s2[tid] + s_s2[Ln + tid] + s_s2[2 * Ln + tid] + s_s2[3 * Ln + tid];

    // Hann half-window at l = tid
    float wl = 0.5f - 0.5f * cosf(3.14159265358979323846f * (float)tid * (1.0f / 255.0f));
    float sw1 = wl * S1;
    float sw2 = (wl * wl) * S2;

    float num_p = sw2;
    float den_p = (sw2 - sw1 * sw1 * (1.0f / (float)Rn)) * (1.0f / (float)(Rn - 1));

    const unsigned FULL = 0xFFFFFFFFu;
#pragma unroll
    for (int off = 16; off > 0; off >>= 1) {
        num_p += __shfl_down_sync(FULL, num_p, off);
        den_p += __shfl_down_sync(FULL, den_p, off);
    }
    const int warp = tid >> 5;
    if (lane == 0) {
        s_red[warp * 2 + 0] = num_p;
        s_red[warp * 2 + 1] = den_p;
    }
    __syncthreads();
    if (warp == 0) {
        float n  = (lane < 8) ? s_red[lane * 2 + 0] : 0.0f;
        float dd = (lane < 8) ? s_red[lane * 2 + 1] : 0.0f;
#pragma unroll
        for (int off = 4; off > 0; off >>= 1) {
            n  += __shfl_down_sync(FULL, n, off);
            dd += __shfl_down_sync(FULL, dd, off);
        }
        if (lane == 0) {
            float num = n * (1.0f / ((float)Rn * (float)Ln));
            float den = dd * (1.0f / (float)Ln) + 0.001f;
            out[(size_t)b1 * B2n + b2] = num / den;
        }
    }
}

extern "C" void kernel_launch(void* const* d_in, const int* in_sizes, int n_in,
                              void* d_out, int out_size)
{
    const float* recordings         = (const float*)d_in[0];
    const float* sample_locations   = (const float*)d_in[1];
    const float* emitter_location   = (const float*)d_in[2];
    const float* receiver_locations = (const float*)d_in[3];
    float* out = (float*)d_out;

    dim3 grid(B2n, B1n);
    dim3 block(Ln);
    tof_predictor_kernel<<<grid, block>>>(recordings, sample_locations,
                                          emitter_location, receiver_locations, out);
}